// round 16
// baseline (speedup 1.0000x reference)
#include <cuda_runtime.h>
#include <cuda_bf16.h>

#define BATCH 4
#define NPTS  16384
#define MCTR  4096
#define KNB   32
#define R2    0.01f
#define RMARG 0.1005f
#define RM2   (RMARG * RMARG)
#define CH    6
#define NCELL 1000          // 10x10x10 per batch
#define TCELL 4096
#define CAP   128
#define NPTOT (BATCH * NPTS)   // 65536
#define BGRID 128              // build blocks: <=148 SMs -> whole grid co-resident

// Scratch (__device__ globals: allocation-guard-safe, zero-initialized)
__device__ float4 g_pts4 [NPTOT];      // orig order (x,y,z,p2)
__device__ float4 g_spts4[NPTOT];      // cell-sorted (x,y,z,bitcast idx)
__device__ int    g_cnt  [TCELL];      // re-zeroed each pass (phase C)
__device__ int    g_off  [TCELL + 1];
__device__ int    g_tick;              // grid barrier 1 (reset by query)
__device__ int    g_flag;              // scan-done flag (reset by query)

// ---------------------------------------------------------------------------
// Fused build: pack+count -> grid barrier -> scan (block 0) -> scatter-from-regs
// Grid of BGRID=128 blocks is provably co-resident => spin barriers are safe.
// ---------------------------------------------------------------------------
__global__ __launch_bounds__(256) void build_kernel(const float* __restrict__ pts) {
    int tid = threadIdx.x;
    int t   = blockIdx.x * 256 + tid;      // 0..32767

    // ---- Phase A: pack + count (2 points/thread, state kept in registers) ----
    float xs[2], ys[2], zs[2];
    int   gcs[2], rks[2], ns[2];
    #pragma unroll
    for (int h = 0; h < 2; h++) {
        int tt = t + h * (NPTOT / 2);
        int b = tt >> 14, n = tt & (NPTS - 1);
        const float* p = pts + (size_t)b * 3 * NPTS;
        float x = p[n], y = p[NPTS + n], z = p[2 * NPTS + n];
        float p2 = __fmaf_rn(z, z, __fmaf_rn(y, y, __fmul_rn(x, x)));
        g_pts4[tt] = make_float4(x, y, z, p2);
        int ci = min(9, max(0, (int)(x * 10.0f)));
        int cj = min(9, max(0, (int)(y * 10.0f)));
        int ck = min(9, max(0, (int)(z * 10.0f)));
        int gc = b * NCELL + (ci * 10 + cj) * 10 + ck;
        int rank = atomicAdd(&g_cnt[gc], 1);
        xs[h] = x; ys[h] = y; zs[h] = z;
        gcs[h] = gc; rks[h] = rank; ns[h] = n;
    }

    // ---- Grid barrier 1: all counts visible ----
    __threadfence();
    __syncthreads();
    if (tid == 0) {
        atomicAdd(&g_tick, 1);
        while (*(volatile int*)&g_tick < BGRID) {}
    }
    __syncthreads();

    // ---- Scan (block 0 only): 4096 counts, 16/thread ----
    if (blockIdx.x == 0) {
        __shared__ int wsums[8];
        int lane = tid & 31, wid = tid >> 5;
        int base = tid * 16;
        int vals[16];
        int tot = 0;
        #pragma unroll
        for (int i = 0; i < 16; i++) { vals[i] = g_cnt[base + i]; tot += vals[i]; }

        int inc = tot;
        #pragma unroll
        for (int d = 1; d < 32; d <<= 1) {
            int u = __shfl_up_sync(0xffffffffu, inc, d);
            if (lane >= d) inc += u;
        }
        if (lane == 31) wsums[wid] = inc;
        __syncthreads();
        if (tid == 0) {
            int run = 0;
            #pragma unroll
            for (int i = 0; i < 8; i++) { int v = wsums[i]; wsums[i] = run; run += v; }
        }
        __syncthreads();

        int run = wsums[wid] + inc - tot;
        #pragma unroll
        for (int i = 0; i < 16; i++) { g_off[base + i] = run; run += vals[i]; }
        if (tid == 255) g_off[TCELL] = run;

        __threadfence();
        __syncthreads();
        if (tid == 0) *(volatile int*)&g_flag = 1;
    } else {
        if (tid == 0) { while (*(volatile int*)&g_flag == 0) {} }
    }
    __syncthreads();

    // ---- Phase C: zero g_cnt slice + scatter straight from registers ----
    if (tid < 32) g_cnt[blockIdx.x * 32 + tid] = 0;
    #pragma unroll
    for (int h = 0; h < 2; h++) {
        int pos = __ldcg(&g_off[gcs[h]]) + rks[h];       // L2 read (fresh)
        g_spts4[pos] = make_float4(xs[h], ys[h], zs[h], __int_as_float(ns[h]));
    }
}

// ---------------------------------------------------------------------------
// warp selection primitives (ascending, 32 elements across lanes)
// ---------------------------------------------------------------------------
__device__ __forceinline__ int sort32(int v, int lane) {
    #pragma unroll
    for (int k = 2; k <= 32; k <<= 1) {
        #pragma unroll
        for (int j = k >> 1; j > 0; j >>= 1) {
            int part = __shfl_xor_sync(0xffffffffu, v, j);
            bool up = ((lane & k) == 0);
            bool takeMin = (((lane & j) == 0) == up);
            v = takeMin ? min(v, part) : max(v, part);
        }
    }
    return v;
}

__device__ __forceinline__ int merge_lower32(int a, int b, int lane) {
    int brev = __shfl_sync(0xffffffffu, b, 31 - lane);
    int m = min(a, brev);
    #pragma unroll
    for (int j = 16; j > 0; j >>= 1) {
        int part = __shfl_xor_sync(0xffffffffu, m, j);
        bool takeMin = ((lane & j) == 0);
        m = takeMin ? min(m, part) : max(m, part);
    }
    return m;
}

// ---------------------------------------------------------------------------
// warp-per-center query + fused grouping epilogue (R14, unchanged)
// ---------------------------------------------------------------------------
__global__ __launch_bounds__(256) void query_kernel(const float* __restrict__ centers,
                                                    float* __restrict__ out) {
    __shared__ int   lists[8][CAP];          // 4 KB
    __shared__ float stage[CH][8][33];       // 6.2 KB

    // reset build-kernel barrier state for the next graph replay
    if (blockIdx.x == 0 && threadIdx.x == 0) { g_tick = 0; g_flag = 0; }

    int gw   = (blockIdx.x * blockDim.x + threadIdx.x) >> 5;
    int wslt = threadIdx.x >> 5;
    int lane = threadIdx.x & 31;
    int b = gw / MCTR, m = gw - b * MCTR;

    const float* c = centers + (size_t)b * 3 * MCTR;
    float cx = c[m], cy = c[MCTR + m], cz = c[2 * MCTR + m];
    float c2 = __fmaf_rn(cz, cz, __fmaf_rn(cy, cy, __fmul_rn(cx, cx)));

    int i0 = max(0, (int)((cx - RMARG) * 10.0f)), i1 = min(9, (int)((cx + RMARG) * 10.0f));
    int j0 = max(0, (int)((cy - RMARG) * 10.0f)), j1 = min(9, (int)((cy + RMARG) * 10.0f));
    int k0 = max(0, (int)((cz - RMARG) * 10.0f)), k1 = min(9, (int)((cz + RMARG) * 10.0f));

    int* lst = lists[wslt];
    unsigned below = (1u << lane) - 1u;
    unsigned cnt = 0;

    for (int ci = i0; ci <= i1; ci++) {
        float lox = ci * 0.1f, hix = lox + 0.1f;
        float dxm = fmaxf(fmaxf(lox - cx, cx - hix), 0.0f);
        float dx2 = dxm * dxm;
        for (int cj = j0; cj <= j1; cj++) {
            float loy = cj * 0.1f, hiy = loy + 0.1f;
            float dym = fmaxf(fmaxf(loy - cy, cy - hiy), 0.0f);
            if (__fmaf_rn(dym, dym, dx2) >= RM2) continue;   // column prune

            int cb = b * NCELL + (ci * 10 + cj) * 10;        // z-cells contiguous
            int start = g_off[cb + k0];
            int end   = g_off[cb + k1 + 1];
            for (int pb = start; pb < end; pb += 64) {
                int p0 = pb + lane;
                int p1 = pb + 32 + lane;
                bool h0 = false, h1 = false;
                int iv0 = 0, iv1 = 0;
                if (p0 < end) {
                    float4 q = g_spts4[p0];
                    float p2 = __fmaf_rn(q.z, q.z, __fmaf_rn(q.y, q.y, __fmul_rn(q.x, q.x)));
                    float cp = __fmaf_rn(cz, q.z, __fmaf_rn(cy, q.y, __fmul_rn(cx, q.x)));
                    float d2 = __fsub_rn(__fadd_rn(c2, p2), __fmul_rn(2.0f, cp));
                    h0 = d2 < R2;
                    iv0 = __float_as_int(q.w);
                }
                if (p1 < end) {
                    float4 q = g_spts4[p1];
                    float p2 = __fmaf_rn(q.z, q.z, __fmaf_rn(q.y, q.y, __fmul_rn(q.x, q.x)));
                    float cp = __fmaf_rn(cz, q.z, __fmaf_rn(cy, q.y, __fmul_rn(cx, q.x)));
                    float d2 = __fsub_rn(__fadd_rn(c2, p2), __fmul_rn(2.0f, cp));
                    h1 = d2 < R2;
                    iv1 = __float_as_int(q.w);
                }
                unsigned m0 = __ballot_sync(0xffffffffu, h0);
                unsigned m1 = __ballot_sync(0xffffffffu, h1);

                unsigned s0 = cnt + __popc(m0 & below);
                if (h0 && s0 < CAP) lst[s0] = iv0;
                unsigned cmid = cnt + __popc(m0);
                unsigned s1 = cmid + __popc(m1 & below);
                if (h1 && s1 < CAP) lst[s1] = iv1;
                cnt = cmid + __popc(m1);
            }
        }
    }

    int eff = min((int)cnt, CAP);
    int ng  = (eff <= 32) ? 1 : (eff <= 64) ? 2 : (eff <= 96) ? 3 : 4;
    for (int t = eff + lane; t < ng * 32; t += 32) lst[t] = 0x7fffffff;
    __syncwarp();

    int top;
    {
        int a = sort32(lst[lane], lane);
        if (ng == 1) {
            top = a;
        } else {
            int bb = sort32(lst[32 + lane], lane);
            int m01 = merge_lower32(a, bb, lane);
            if (ng == 2) {
                top = m01;
            } else {
                int cc = sort32(lst[64 + lane], lane);
                if (ng == 3) {
                    top = merge_lower32(m01, cc, lane);
                } else {
                    int dd = sort32(lst[96 + lane], lane);
                    top = merge_lower32(m01, merge_lower32(cc, dd, lane), lane);
                }
            }
        }
    }

    // ----- fused grouping epilogue -----
    int topidx = (lane < eff) ? top : 0;                 // reference zero-pads
    float4 pq = g_pts4[(size_t)b * NPTS + topidx];

    stage[0][wslt][lane] = pq.x;
    stage[1][wslt][lane] = pq.y;
    stage[2][wslt][lane] = pq.z;
    stage[3][wslt][lane] = __fsub_rn(pq.x, cx);
    stage[4][wslt][lane] = __fsub_rn(pq.y, cy);
    stage[5][wslt][lane] = __fsub_rn(pq.z, cz);
    __syncthreads();

    int tid   = threadIdx.x;
    int mbase = (blockIdx.x * 8) & (MCTR - 1);
    float* ob = out + (size_t)b * (CH * KNB) * MCTR + mbase;

    #pragma unroll
    for (int pass = 0; pass < 2; pass++) {
        int r = (tid >> 1) + pass * 128;
        if (r < CH * KNB) {
            int cch = r >> 5, kk = r & 31;
            int mh = (tid & 1) * 4;
            float v0 = stage[cch][mh + 0][kk];
            float v1 = stage[cch][mh + 1][kk];
            float v2 = stage[cch][mh + 2][kk];
            float v3 = stage[cch][mh + 3][kk];
            *reinterpret_cast<float4*>(ob + (size_t)r * MCTR + mh) =
                make_float4(v0, v1, v2, v3);
        }
    }
}

// ---------------------------------------------------------------------------
extern "C" void kernel_launch(void* const* d_in, const int* in_sizes, int n_in,
                              void* d_out, int out_size) {
    const float* pts = (const float*)d_in[0];
    const float* ctr = (const float*)d_in[1];
    if (n_in >= 2 && in_sizes[0] < in_sizes[1]) {
        const float* t = pts; pts = ctr; ctr = t;
    }
    float* out = (float*)d_out;

    build_kernel<<<BGRID, 256>>>(pts);
    query_kernel<<<(BATCH * MCTR) / 8, 256>>>(ctr, out);
}